// round 7
// baseline (speedup 1.0000x reference)
#include <cuda_runtime.h>
#include <math.h>
#include <stdint.h>

// ---------------------------------------------------------------------------
// Problem constants
// ---------------------------------------------------------------------------
#define Bq      8
#define NFULL   4096
#define NLAT    1024
#define CDIM    256
#define HEADS   8
#define VDIM    32
#define MBIG    (Bq*NFULL)   // 32768
#define MLAT    (Bq*NLAT)    // 8192

// ---------------------------------------------------------------------------
// Scratch (device globals; no allocation allowed)
// ---------------------------------------------------------------------------
__device__ float g_big0[MBIG*CDIM];   // h0 / up-attn output
__device__ float g_big1[MBIG*CDIM];   // down value / de_fc1 output
__device__ float g_lat [MLAT*CDIM];   // latent h
__device__ float g_pa  [MLAT*CDIM];   // pos_att output (latent blocks)
__device__ float g_t1  [MLAT*CDIM];   // value (latent) / fc1 output
__device__ float g_t3  [MLAT*CDIM];   // residual branch
__device__ float g_wcat[CDIM*CDIM];   // repacked per-head attention value weight
__device__ float g_smin[HEADS*NFULL]; // per-(h,row) sd min
__device__ float g_sinv[HEADS*NFULL]; // per-(h,row) 1/denominator
__device__ float g_sthr[HEADS*NFULL]; // per-(h,row) threshold (inf for global)

// ---------------------------------------------------------------------------
// Helpers
// ---------------------------------------------------------------------------
__device__ __forceinline__ float gelu_f(float v){
    // JAX default gelu (approximate=True): 0.5*x*(1+tanh(sqrt(2/pi)*(x+0.044715 x^3)))
    float t = tanhf(0.7978845608028654f * (v + 0.044715f * v * v * v));
    return 0.5f * v * (1.0f + t);
}

__device__ __forceinline__ float scale_from_r(float r){
    // 0.25*pi*(1-1e-7) computed in f64, rounded to f32 (matches JAX weak-typing)
    const float A = 0.7853980848576320f;
    return tanf(A * (1.0f + sinf(r)));
}

// ---------------------------------------------------------------------------
// Encoder: out = gelu(x @ W[4,256] + b), one block per row
// ---------------------------------------------------------------------------
__global__ void encoder_kernel(const float* __restrict__ x,
                               const float* __restrict__ W,
                               const float* __restrict__ bias,
                               float* __restrict__ out){
    int m = blockIdx.x;
    int c = threadIdx.x;
    const float* xr = x + (size_t)m * 4;
    float v = bias[c];
    v += xr[0]*W[c] + xr[1]*W[256+c] + xr[2]*W[512+c] + xr[3]*W[768+c];
    out[(size_t)m*256 + c] = gelu_f(v);
}

// ---------------------------------------------------------------------------
// Repack per-head value weight [H,C,VD] -> [C, H*VD] (col = h*32+k)
// ---------------------------------------------------------------------------
__global__ void repack_w_kernel(const float* __restrict__ w, float* __restrict__ wcat){
    int idx = blockIdx.x * 256 + threadIdx.x;   // 65536 total
    int j = idx >> 8;
    int c = idx & 255;
    int h = c >> 5;
    int k = c & 31;
    wcat[idx] = w[h*(CDIM*VDIM) + j*VDIM + k];
}

// ---------------------------------------------------------------------------
// Generic GEMM: out[M,256] = epi(A[M,256] @ W[256,256] [+bias] [+addin]) [gelu]
// 64x256 tile per block, 8x8 microtile per thread, K tiles of 32.
// ---------------------------------------------------------------------------
template<bool BIAS, bool GELU, bool ADDIN>
__global__ __launch_bounds__(256)
void gemm256_kernel(const float* __restrict__ A, const float* __restrict__ W,
                    const float* __restrict__ bias, const float* __restrict__ addin,
                    float* __restrict__ out){
    __shared__ float As[64][36];
    __shared__ float Ws[32][256];
    int tid = threadIdx.x;
    int j0  = blockIdx.x * 64;
    int jb  = tid >> 5;       // 0..7 (row octet)
    int cb  = tid & 31;       // 0..31 (col octet)

    float acc[8][8];
    #pragma unroll
    for (int u=0;u<8;u++)
        #pragma unroll
        for (int v=0;v<8;v++) acc[u][v]=0.f;

    for (int k0 = 0; k0 < 256; k0 += 32){
        #pragma unroll
        for (int i=0;i<2;i++){
            int id = tid + 256*i;
            int j = id >> 3, q = id & 7;
            float4 a4 = *reinterpret_cast<const float4*>(A + (size_t)(j0+j)*256 + k0 + q*4);
            As[j][q*4+0]=a4.x; As[j][q*4+1]=a4.y; As[j][q*4+2]=a4.z; As[j][q*4+3]=a4.w;
        }
        #pragma unroll
        for (int i=0;i<8;i++){
            int id = tid + 256*i;
            int kk = id >> 6, f = id & 63;
            float4 w4 = *reinterpret_cast<const float4*>(W + (size_t)(k0+kk)*256 + f*4);
            *reinterpret_cast<float4*>(&Ws[kk][f*4]) = w4;
        }
        __syncthreads();
        #pragma unroll
        for (int kk=0; kk<32; kk++){
            float a[8], w[8];
            #pragma unroll
            for (int u=0;u<8;u++) a[u] = As[jb*8+u][kk];   // warp-broadcast
            float4 w0 = *reinterpret_cast<const float4*>(&Ws[kk][cb*8]);
            float4 w1 = *reinterpret_cast<const float4*>(&Ws[kk][cb*8+4]);
            w[0]=w0.x; w[1]=w0.y; w[2]=w0.z; w[3]=w0.w;
            w[4]=w1.x; w[5]=w1.y; w[6]=w1.z; w[7]=w1.w;
            #pragma unroll
            for (int u=0;u<8;u++)
                #pragma unroll
                for (int v=0;v<8;v++) acc[u][v] += a[u]*w[v];
        }
        __syncthreads();
    }

    float br[8];
    if (BIAS){
        #pragma unroll
        for (int v=0;v<8;v++) br[v] = bias[cb*8+v];
    }
    #pragma unroll
    for (int u=0;u<8;u++){
        size_t base = (size_t)(j0 + jb*8 + u)*256 + cb*8;
        float vals[8];
        #pragma unroll
        for (int v=0;v<8;v++){
            float t = acc[u][v];
            if (BIAS)  t += br[v];
            if (ADDIN) t += addin[base+v];
            if (GELU)  t = gelu_f(t);
            vals[v]=t;
        }
        *reinterpret_cast<float4*>(out+base)   = make_float4(vals[0],vals[1],vals[2],vals[3]);
        *reinterpret_cast<float4*>(out+base+4) = make_float4(vals[4],vals[5],vals[6],vals[7]);
    }
}

// ---------------------------------------------------------------------------
// Softmax stats (global, no mask): per row min(sd) and 1/sum(exp(min-sd)); thr=inf
// One block (256 thr) per (h,row); row data cached in dynamic smem.
// ---------------------------------------------------------------------------
__global__ void stats_global_kernel(const float* __restrict__ m,
                                    const float* __restrict__ r,
                                    float* __restrict__ sdmin, float* __restrict__ invden,
                                    float* __restrict__ thr, int Nq, int Nk){
    extern __shared__ float sbuf[];
    __shared__ float red[256];
    int row = blockIdx.x;
    int h = row / Nq;
    float scale = scale_from_r(r[h]);
    const float* mr = m + (size_t)row * Nk;
    float lmin = 3.402823466e38f;
    for (int i = threadIdx.x; i < Nk; i += 256){
        float sd = mr[i] * scale;
        sbuf[i] = sd;
        lmin = fminf(lmin, sd);
    }
    red[threadIdx.x] = lmin;
    __syncthreads();
    for (int s=128; s>0; s>>=1){
        if (threadIdx.x < s) red[threadIdx.x] = fminf(red[threadIdx.x], red[threadIdx.x+s]);
        __syncthreads();
    }
    float mn = red[0];
    __syncthreads();
    float ls = 0.f;
    for (int i = threadIdx.x; i < Nk; i += 256) ls += __expf(mn - sbuf[i]);
    red[threadIdx.x] = ls;
    __syncthreads();
    for (int s=128; s>0; s>>=1){
        if (threadIdx.x < s) red[threadIdx.x] += red[threadIdx.x+s];
        __syncthreads();
    }
    if (threadIdx.x == 0){
        sdmin[row]  = mn;
        invden[row] = 1.0f / red[0];
        thr[row]    = __int_as_float(0x7f800000);  // +inf
    }
}

// ---------------------------------------------------------------------------
// Softmax stats (local, 30th percentile mask), Nk=1024 fixed.
// Bitonic sort in smem, linear-interp percentile, masked denom.
// ---------------------------------------------------------------------------
__global__ void stats_local_kernel(const float* __restrict__ m,
                                   const float* __restrict__ r,
                                   float* __restrict__ sdmin, float* __restrict__ invden,
                                   float* __restrict__ thr, int Nq){
    __shared__ float s[1024];
    __shared__ float red[256];
    int row = blockIdx.x;
    int h = row / Nq;
    float scale = scale_from_r(r[h]);
    const float* mr = m + (size_t)row * 1024;
    for (int i = threadIdx.x; i < 1024; i += 256) s[i] = mr[i] * scale;
    __syncthreads();
    // bitonic sort ascending
    for (int k = 2; k <= 1024; k <<= 1){
        for (int j = k >> 1; j > 0; j >>= 1){
            for (int i = threadIdx.x; i < 1024; i += 256){
                int ixj = i ^ j;
                if (ixj > i){
                    bool up = ((i & k) == 0);
                    float a = s[i], b = s[ixj];
                    if ((a > b) == up){ s[i] = b; s[ixj] = a; }
                }
            }
            __syncthreads();
        }
    }
    float pos = 1023.0f * (30.0f / 100.0f);   // 306.9
    int lo = (int)pos;
    float fr = pos - (float)lo;
    float th = s[lo] + fr * (s[lo+1] - s[lo]);
    float mn = s[0];
    float ls = 0.f;
    for (int i = threadIdx.x; i < 1024; i += 256){
        float v = s[i];
        if (v <= th) ls += __expf(mn - v);
    }
    red[threadIdx.x] = ls;
    __syncthreads();
    for (int st=128; st>0; st>>=1){
        if (threadIdx.x < st) red[threadIdx.x] += red[threadIdx.x+st];
        __syncthreads();
    }
    if (threadIdx.x == 0){
        sdmin[row]  = mn;
        invden[row] = 1.0f / red[0];
        thr[row]    = th;
    }
}

// ---------------------------------------------------------------------------
// Attention apply: out[b, j, h*32+k] = gelu( sum_n p[h,j,n] * V[b,n,h*32+k] )
// p computed on the fly from m_dist + stats. Block = (64 j-rows) x (head).
// Output columns = 256 = (b,k) pairs. Same 8x8 microkernel as gemm256.
// ---------------------------------------------------------------------------
__global__ __launch_bounds__(256)
void attn_apply_kernel(const float* __restrict__ m_dist,  // [H,Nq,Nk]
                       const float* __restrict__ r,       // [H]
                       const float* __restrict__ sdmin,
                       const float* __restrict__ invden,
                       const float* __restrict__ thr,
                       const float* __restrict__ V,       // [B, Nk, 256]
                       float* __restrict__ out,           // [B, Nq, 256]
                       int Nq, int Nk){
    __shared__ float Ps[64][36];     // [j][nn]
    __shared__ float Vs[32][256];    // [nn][c], c = b*32+k
    __shared__ float s_min[64], s_inv[64], s_thr[64];
    int tid = threadIdx.x;
    int h  = blockIdx.y;
    int j0 = blockIdx.x * 64;
    float scale = scale_from_r(r[h]);
    if (tid < 64){
        int row = h*Nq + j0 + tid;
        s_min[tid] = sdmin[row];
        s_inv[tid] = invden[row];
        s_thr[tid] = thr[row];
    }
    __syncthreads();
    int jb = tid >> 5;
    int cb = tid & 31;
    int b  = cb >> 2;             // (cb*8)/32
    int kbase = (cb & 3) * 8;

    float acc[8][8];
    #pragma unroll
    for (int u=0;u<8;u++)
        #pragma unroll
        for (int v=0;v<8;v++) acc[u][v]=0.f;

    const float* mbase = m_dist + ((size_t)h*Nq + j0) * Nk;

    for (int n0 = 0; n0 < Nk; n0 += 32){
        // fill P (weights): 64x32, 2 float4 per thread
        #pragma unroll
        for (int i=0;i<2;i++){
            int id = tid + 256*i;
            int j = id >> 3, q = id & 7;
            float4 m4 = *reinterpret_cast<const float4*>(mbase + (size_t)j*Nk + n0 + q*4);
            float mn = s_min[j], iv = s_inv[j], th = s_thr[j];
            float sd0 = m4.x*scale, sd1 = m4.y*scale, sd2 = m4.z*scale, sd3 = m4.w*scale;
            Ps[j][q*4+0] = (sd0 <= th) ? __expf(mn - sd0)*iv : 0.f;
            Ps[j][q*4+1] = (sd1 <= th) ? __expf(mn - sd1)*iv : 0.f;
            Ps[j][q*4+2] = (sd2 <= th) ? __expf(mn - sd2)*iv : 0.f;
            Ps[j][q*4+3] = (sd3 <= th) ? __expf(mn - sd3)*iv : 0.f;
        }
        // fill V tile: 32 x 256 floats
        #pragma unroll
        for (int i=0;i<8;i++){
            int id = tid + 256*i;
            int nn = id >> 6, f = id & 63;
            int bb = f >> 3, kq = f & 7;
            float4 v4 = *reinterpret_cast<const float4*>(
                V + ((size_t)bb*Nk + n0 + nn)*256 + h*32 + kq*4);
            *reinterpret_cast<float4*>(&Vs[nn][bb*32 + kq*4]) = v4;
        }
        __syncthreads();
        #pragma unroll
        for (int nn=0; nn<32; nn++){
            float p[8], w[8];
            #pragma unroll
            for (int u=0;u<8;u++) p[u] = Ps[jb*8+u][nn];   // warp-broadcast
            float4 v0 = *reinterpret_cast<const float4*>(&Vs[nn][cb*8]);
            float4 v1 = *reinterpret_cast<const float4*>(&Vs[nn][cb*8+4]);
            w[0]=v0.x; w[1]=v0.y; w[2]=v0.z; w[3]=v0.w;
            w[4]=v1.x; w[5]=v1.y; w[6]=v1.z; w[7]=v1.w;
            #pragma unroll
            for (int u=0;u<8;u++)
                #pragma unroll
                for (int v=0;v<8;v++) acc[u][v] += p[u]*w[v];
        }
        __syncthreads();
    }

    // epilogue: gelu, scatter to [B, Nq, 256]
    #pragma unroll
    for (int u=0;u<8;u++){
        int row = j0 + jb*8 + u;
        float* o = out + ((size_t)b*Nq + row)*256 + h*32 + kbase;
        float vals[8];
        #pragma unroll
        for (int v=0;v<8;v++) vals[v] = gelu_f(acc[u][v]);
        *reinterpret_cast<float4*>(o)   = make_float4(vals[0],vals[1],vals[2],vals[3]);
        *reinterpret_cast<float4*>(o+4) = make_float4(vals[4],vals[5],vals[6],vals[7]);
    }
}

// ---------------------------------------------------------------------------
// Final dense 256 -> 1 (one warp per row)
// ---------------------------------------------------------------------------
__global__ void final_dense_kernel(const float* __restrict__ hin,
                                   const float* __restrict__ w,
                                   const float* __restrict__ bias,
                                   float* __restrict__ out){
    int warp = threadIdx.x >> 5;
    int lane = threadIdx.x & 31;
    int row = blockIdx.x * 8 + warp;
    const float* hr = hin + (size_t)row * 256;
    float s = 0.f;
    #pragma unroll
    for (int i = 0; i < 8; i++) s += hr[lane + 32*i] * w[lane + 32*i];
    #pragma unroll
    for (int off = 16; off; off >>= 1) s += __shfl_xor_sync(0xffffffff, s, off);
    if (lane == 0) out[row] = s + bias[0];
}

// ---------------------------------------------------------------------------
// Host orchestration
// ---------------------------------------------------------------------------
extern "C" void kernel_launch(void* const* d_in, const int* in_sizes, int n_in,
                              void* d_out, int out_size){
    const float* x      = (const float*)d_in[0];
    const float* m_down = (const float*)d_in[1];
    const float* m_p[2] = {(const float*)d_in[2], (const float*)d_in[3]};
    const float* m_up   = (const float*)d_in[4];
    const float* en_w   = (const float*)d_in[5];
    const float* en_b   = (const float*)d_in[6];
    const float* down_r = (const float*)d_in[7];
    const float* down_w = (const float*)d_in[8];
    const float* pa_r[2]= {(const float*)d_in[9],  (const float*)d_in[17]};
    const float* pa_w[2]= {(const float*)d_in[10], (const float*)d_in[18]};
    const float* f1w[2] = {(const float*)d_in[11], (const float*)d_in[19]};
    const float* f1b[2] = {(const float*)d_in[12], (const float*)d_in[20]};
    const float* f2w[2] = {(const float*)d_in[13], (const float*)d_in[21]};
    const float* f2b[2] = {(const float*)d_in[14], (const float*)d_in[22]};
    const float* rw[2]  = {(const float*)d_in[15], (const float*)d_in[23]};
    const float* rb[2]  = {(const float*)d_in[16], (const float*)d_in[24]};
    const float* up_r   = (const float*)d_in[25];
    const float* up_w   = (const float*)d_in[26];
    const float* de1w   = (const float*)d_in[27];
    const float* de1b   = (const float*)d_in[28];
    const float* de2w   = (const float*)d_in[29];
    const float* de2b   = (const float*)d_in[30];
    float* outp = (float*)d_out;

    float *b0, *b1, *lat, *pa, *t1, *t3, *wcat, *smin, *sinv, *sthr;
    cudaGetSymbolAddress((void**)&b0,   g_big0);
    cudaGetSymbolAddress((void**)&b1,   g_big1);
    cudaGetSymbolAddress((void**)&lat,  g_lat);
    cudaGetSymbolAddress((void**)&pa,   g_pa);
    cudaGetSymbolAddress((void**)&t1,   g_t1);
    cudaGetSymbolAddress((void**)&t3,   g_t3);
    cudaGetSymbolAddress((void**)&wcat, g_wcat);
    cudaGetSymbolAddress((void**)&smin, g_smin);
    cudaGetSymbolAddress((void**)&sinv, g_sinv);
    cudaGetSymbolAddress((void**)&sthr, g_sthr);

    // 1. encoder: h0 = gelu(x @ en_w + en_b)   -> b0  [B*NFULL, 256]
    encoder_kernel<<<MBIG, 256>>>(x, en_w, en_b, b0);

    // 2. down pos_att (global)
    repack_w_kernel<<<256, 256>>>(down_w, wcat);
    gemm256_kernel<false,false,false><<<MBIG/64, 256>>>(b0, wcat, nullptr, nullptr, b1); // value
    stats_global_kernel<<<HEADS*NLAT, 256, NFULL*4>>>(m_down, down_r, smin, sinv, sthr, NLAT, NFULL);
    attn_apply_kernel<<<dim3(NLAT/64, HEADS), 256>>>(m_down, down_r, smin, sinv, sthr,
                                                     b1, lat, NLAT, NFULL);

    // 3. latent blocks (local, 30th percentile)
    for (int blk = 0; blk < 2; blk++){
        stats_local_kernel<<<HEADS*NLAT, 256>>>(m_p[blk], pa_r[blk], smin, sinv, sthr, NLAT);
        repack_w_kernel<<<256, 256>>>(pa_w[blk], wcat);
        gemm256_kernel<false,false,false><<<MLAT/64, 256>>>(lat, wcat, nullptr, nullptr, t1); // value
        attn_apply_kernel<<<dim3(NLAT/64, HEADS), 256>>>(m_p[blk], pa_r[blk], smin, sinv, sthr,
                                                         t1, pa, NLAT, NLAT);
        gemm256_kernel<true,true,false><<<MLAT/64, 256>>>(pa, f1w[blk], f1b[blk], nullptr, t1); // gelu(fc1)
        gemm256_kernel<true,false,false><<<MLAT/64, 256>>>(lat, rw[blk], rb[blk], nullptr, t3); // residual
        gemm256_kernel<true,true,true><<<MLAT/64, 256>>>(t1, f2w[blk], f2b[blk], t3, lat);      // gelu(fc2+res)
    }

    // 4. up pos_att (global)
    stats_global_kernel<<<HEADS*NFULL, 256, NLAT*4>>>(m_up, up_r, smin, sinv, sthr, NFULL, NLAT);
    repack_w_kernel<<<256, 256>>>(up_w, wcat);
    gemm256_kernel<false,false,false><<<MLAT/64, 256>>>(lat, wcat, nullptr, nullptr, t1);  // value
    attn_apply_kernel<<<dim3(NFULL/64, HEADS), 256>>>(m_up, up_r, smin, sinv, sthr,
                                                      t1, b0, NFULL, NLAT);

    // 5. decoder
    gemm256_kernel<true,true,false><<<MBIG/64, 256>>>(b0, de1w, de1b, nullptr, b1);  // gelu(de_fc1)
    final_dense_kernel<<<MBIG/8, 256>>>(b1, de2w, de2b, outp);                       // de_fc2
}